// round 16
// baseline (speedup 1.0000x reference)
#include <cuda_runtime.h>
#include <cuda_fp16.h>
#include <cstdint>

// Problem constants
#define NE 8
#define NH 2048
#define NI 1408
#define NT 2048
#define NK 2
#define NG 128
#define NPAIR (NT * NK)   // 4096
#define BM 128
#define MB (NPAIR / BM)   // 32

// ---------------- scratch ----------------
__device__ int    g_off[NE + 1];
__device__ int    g_pairs[NPAIR];
__device__ __half g_xh[NT][NH];               // x in fp16
__device__ __half g_h[NPAIR][NI];             // silu(g)*u / 32
__device__ __half g_wgu[NE][2 * NI][NH];      // gate/up fp16 (raw*2^-14), row = 2i+mat
__device__ __half g_wd[NE][NH][NI];           // down fp16 (raw*2^-14)

// ---------------- helpers ----------------
__device__ __forceinline__ uint32_t smem_u32(const void* p) {
    uint32_t a;
    asm("{ .reg .u64 t; cvta.to.shared.u64 t, %1; cvt.u32.u64 %0, t; }" : "=r"(a) : "l"(p));
    return a;
}
__device__ __forceinline__ void ldsm4(unsigned* r, uint32_t addr) {
    asm volatile("ldmatrix.sync.aligned.m8n8.x4.shared.b16 {%0,%1,%2,%3},[%4];"
                 : "=r"(r[0]), "=r"(r[1]), "=r"(r[2]), "=r"(r[3]) : "r"(addr));
}
__device__ __forceinline__ void mma16816(float* c, const unsigned* a, const unsigned* b) {
    asm volatile(
        "mma.sync.aligned.m16n8k16.row.col.f32.f16.f16.f32 "
        "{%0,%1,%2,%3},{%4,%5,%6,%7},{%8,%9},{%0,%1,%2,%3};"
        : "+f"(c[0]), "+f"(c[1]), "+f"(c[2]), "+f"(c[3])
        : "r"(a[0]), "r"(a[1]), "r"(a[2]), "r"(a[3]), "r"(b[0]), "r"(b[1]));
}
__device__ __forceinline__ void cp_async16(uint32_t dst, const void* src) {
    asm volatile("cp.async.cg.shared.global [%0], [%1], 16;" :: "r"(dst), "l"(src));
}
#define CP_COMMIT asm volatile("cp.async.commit_group;" ::: "memory")
#define CP_WAIT0  asm volatile("cp.async.wait_group 0;" ::: "memory")

// 8 e2m1 nibbles -> 8 fp16 encoding value * 2^-14 (exact, incl. subnormals).
__device__ __forceinline__ unsigned dec_pair(unsigned u) {
    return ((u << 9) & 0x0E000E00u) | ((u << 12) & 0x80008000u);
}
__device__ __forceinline__ uint4 dec_word_raw(unsigned p) {
    unsigned e = p & 0x0F0F0F0Fu;
    unsigned o = (p >> 4) & 0x0F0F0F0Fu;
    uint4 r;
    r.x = dec_pair(__byte_perm(e, o, 0x0400));
    r.y = dec_pair(__byte_perm(e, o, 0x0501));
    r.z = dec_pair(__byte_perm(e, o, 0x0602));
    r.w = dec_pair(__byte_perm(e, o, 0x0703));
    return r;
}
__device__ __forceinline__ uint4 f8_to_h8(float4 v0, float4 v1) {
    __half2 a = __floats2half2_rn(v0.x, v0.y);
    __half2 b = __floats2half2_rn(v0.z, v0.w);
    __half2 c = __floats2half2_rn(v1.x, v1.y);
    __half2 d = __floats2half2_rn(v1.z, v1.w);
    return make_uint4(*(unsigned*)&a, *(unsigned*)&b, *(unsigned*)&c, *(unsigned*)&d);
}

// ---------------- fused prep + weight predecode + routing ----------------
#define NB_PREP (NT * NH / 16 / 256)            // 1024
#define NB_GU   (NE * 2 * NI * 128 / 256)       // 11264 (uint2 units, 128/row)
#define NB_DN   (NE * NH * 88 / 256)            // 5632  (uint2 units, 88/row)

__global__ void k_front(const float* __restrict__ x,
                        const unsigned* __restrict__ gp_,
                        const unsigned* __restrict__ up_,
                        const unsigned* __restrict__ dp_,
                        const int* __restrict__ topk_idx) {
    unsigned b = blockIdx.x;
    if (b < NB_PREP) {
        int idx = b * 256 + threadIdx.x;        // over NT*NH/16
        const float4* p = reinterpret_cast<const float4*>(x) + (size_t)idx * 4;
        float4 v0 = p[0], v1 = p[1], v2 = p[2], v3 = p[3];
        uint4* dst = reinterpret_cast<uint4*>(&g_xh[0][0] + (size_t)idx * 16);
        dst[0] = f8_to_h8(v0, v1);
        dst[1] = f8_to_h8(v2, v3);
        return;
    }
    b -= NB_PREP;
    if (b < NB_GU) {
        // gate/up predecode: one uint2 (2 packed words = 16 nibbles) per thread
        int t = b * 256 + threadIdx.x;          // over NE*2*NI*128
        int er  = t >> 7;                       // global row 0..NE*2*NI-1
        int pos = t & 127;                      // uint2 index within row
        int e = er / (2 * NI), r = er % (2 * NI);
        int i = r >> 1, mat = r & 1;
        const unsigned* src = (mat ? up_ : gp_) + ((size_t)e * NI + i) * (NH / 8) + pos * 2;
        uint2 w = *(const uint2*)src;
        uint4* dst = (uint4*)(&g_wgu[0][0][0] + (size_t)er * NH + pos * 16);
        dst[0] = dec_word_raw(w.x);
        dst[1] = dec_word_raw(w.y);
        return;
    }
    b -= NB_GU;
    if (b < NB_DN) {
        int t = b * 256 + threadIdx.x;          // over NE*NH*88
        int er  = t / 88;
        int pos = t % 88;
        const unsigned* src = dp_ + (size_t)er * (NI / 8) + pos * 2;
        uint2 w = *(const uint2*)src;
        uint4* dst = (uint4*)(&g_wd[0][0][0] + (size_t)er * NI + pos * 16);
        dst[0] = dec_word_raw(w.x);
        dst[1] = dec_word_raw(w.y);
        return;
    }
    // routing (last block)
    __shared__ int s_cnt[NE];
    __shared__ int s_off[NE + 1];
    int tid = threadIdx.x;
    if (tid < NE) s_cnt[tid] = 0;
    __syncthreads();
    for (int p = tid; p < NPAIR; p += 256)
        atomicAdd(&s_cnt[topk_idx[p]], 1);
    __syncthreads();
    if (tid == 0) {
        int acc = 0;
        for (int e = 0; e < NE; e++) { s_off[e] = acc; acc += s_cnt[e]; s_cnt[e] = 0; }
        s_off[NE] = acc;
        for (int e = 0; e <= NE; e++) g_off[e] = s_off[e];
    }
    __syncthreads();
    for (int p = tid; p < NPAIR; p += 256) {
        int e = topk_idx[p];
        int pos = s_off[e] + atomicAdd(&s_cnt[e], 1);
        g_pairs[pos] = p;
    }
}

// =========================================================================
// smem: A 2x16KB @0/16384 ; B 2x16KB @32768/49152 ; rtab @65536 ; tables
// =========================================================================
#define A_BUF(i) ((i) * 16384)
#define B_BUF(i) (32768 + (i) * 16384)
#define GU_SMEM (65536 + 8192 + 1024)
#define DN_SMEM (65536 + 5632 + 512)

__global__ void __launch_bounds__(256, 2) k_gateup(
    const float* __restrict__ gs_,
    const float* __restrict__ us_)
{
    int e = blockIdx.y / MB, mb = blockIdx.y % MB;
    int start = g_off[e], end = g_off[e + 1];
    int m0 = start + mb * BM;
    if (m0 >= end) return;
    int rows = min(BM, end - m0);
    int i0 = blockIdx.x * 64;

    extern __shared__ __align__(16) char smem[];
    uint32_t sb = smem_u32(smem);
    float* rtab = (float*)(smem + 65536);
    int* s_pair = (int*)(smem + 65536 + 8192);
    int* s_tok  = (int*)(smem + 65536 + 8192 + 512);

    int tid = threadIdx.x, warp = tid >> 5, lane = tid & 31;
    if (tid < BM) {
        int pr = g_pairs[m0 + (tid < rows ? tid : 0)];
        s_pair[tid] = pr;
        s_tok[tid]  = pr / NK;
    }
    for (int t = tid; t < 16 * 128; t += 256) {
        int g = t >> 7, n = t & 127;
        const float* arr = ((n & 1) ? us_ : gs_) + (size_t)e * 16 * NI + (i0 + (n >> 1));
        float sg = arr[(size_t)g * NI];
        rtab[t] = (g < 15) ? sg / arr[(size_t)(g + 1) * NI] : sg * 16384.f;
    }
    __syncthreads();

    // staging roles: A row = tid>>1 (4 chunks), B row = tid>>1 (4 chunks)
    int ar = tid >> 1, ac = (tid & 1) * 4;
    const __half* asrc = &g_xh[s_tok[ar]][0];
    int wn_row = tid >> 1, wwb = (tid & 1) * 4;
    const __half* bsrc = &g_wgu[e][2 * i0 + wn_row][0];
    unsigned a_perm = ar & 7, b_perm = wn_row & 7;
    uint32_t a_st[2], b_st[2];
    a_st[0] = sb + A_BUF(0) + ar * 128;     a_st[1] = a_st[0] + 16384;
    b_st[0] = sb + B_BUF(0) + wn_row * 128; b_st[1] = b_st[0] + 16384;

    // mma roles: 4 m-warps x 2 n-warps
    int wm = warp & 3, wn = warp >> 2;
    int q = lane & 3;
    uint32_t colk[4];
    #pragma unroll
    for (int kk = 0; kk < 4; ++kk)
        colk[kk] = (((kk * 2 + (lane >> 4)) ^ (lane & 7)) << 4);
    uint32_t a_base[2], b_base[2];
    a_base[0] = sb + A_BUF(0) + (wm * 32 + (lane & 15)) * 128;
    a_base[1] = a_base[0] + 16384;
    b_base[0] = sb + B_BUF(0) + (wn * 64 + (lane & 15)) * 128;
    b_base[1] = b_base[0] + 16384;
    int rt_half = wn * 32 + q;

    float c[2][8][4];
    #pragma unroll
    for (int a = 0; a < 2; a++)
        #pragma unroll
        for (int b = 0; b < 8; b++)
            #pragma unroll
            for (int z = 0; z < 4; z++) c[a][b][z] = 0.f;

    const int S = NH / 64;   // 32

    // ---- prologue: stage 0 A+B via cp.async
    {
        #pragma unroll
        for (int j = 0; j < 4; ++j)
            cp_async16(a_st[0] + (((ac + j) ^ a_perm) << 4), asrc + (ac + j) * 8);
        #pragma unroll
        for (int j = 0; j < 4; ++j)
            cp_async16(b_st[0] + (((wwb + j) ^ b_perm) << 4), bsrc + (wwb + j) * 8);
        CP_COMMIT;
        CP_WAIT0;
    }
    __syncthreads();

    #pragma unroll 2
    for (int s = 0; s < S; ++s) {
        if (s + 1 < S) {
            int nb = (s + 1) & 1;
            #pragma unroll
            for (int j = 0; j < 4; ++j)
                cp_async16(a_st[nb] + (((ac + j) ^ a_perm) << 4),
                           asrc + (s + 1) * 64 + (ac + j) * 8);
            #pragma unroll
            for (int j = 0; j < 4; ++j)
                cp_async16(b_st[nb] + (((wwb + j) ^ b_perm) << 4),
                           bsrc + (s + 1) * 64 + (wwb + j) * 8);
            CP_COMMIT;
        }
        // MMA on A[s&1], B[s&1]
        {
            uint32_t ab = a_base[s & 1];
            uint32_t bb = b_base[s & 1];
            #pragma unroll
            for (int kk = 0; kk < 4; ++kk) {
                unsigned a0[4], a1[4];
                ldsm4(a0, ab + colk[kk]);
                ldsm4(a1, ab + 2048 + colk[kk]);
                #pragma unroll
                for (int nj = 0; nj < 4; ++nj) {
                    unsigned bf[4];
                    ldsm4(bf, bb + nj * 2048 + colk[kk]);
                    unsigned b0[2] = {bf[0], bf[2]}, b1[2] = {bf[1], bf[3]};
                    mma16816(c[0][nj * 2 + 0], a0, b0);
                    mma16816(c[0][nj * 2 + 1], a0, b1);
                    mma16816(c[1][nj * 2 + 0], a1, b0);
                    mma16816(c[1][nj * 2 + 1], a1, b1);
                }
            }
        }
        if (s & 1) {
            const float2* rt = (const float2*)(rtab + (s >> 1) * 128);
            #pragma unroll
            for (int nj = 0; nj < 4; ++nj)
                #pragma unroll
                for (int hf = 0; hf < 2; ++hf) {
                    float2 r2 = rt[rt_half + nj * 8 + hf * 4];
                    float* c0 = c[0][nj * 2 + hf];
                    float* c1 = c[1][nj * 2 + hf];
                    c0[0] *= r2.x; c0[1] *= r2.y; c0[2] *= r2.x; c0[3] *= r2.y;
                    c1[0] *= r2.x; c1[1] *= r2.y; c1[2] *= r2.x; c1[3] *= r2.y;
                }
        }
        if (s + 1 < S) { CP_WAIT0; }
        __syncthreads();
    }

    // ---- epilogue: silu(g)*u -> smem (row stride 72 halves = 144B), then coalesced g_h
    {
        __half* hst = (__half*)smem;
        int r0 = lane >> 2;
        #pragma unroll
        for (int mi = 0; mi < 2; ++mi) {
            #pragma unroll
            for (int nj = 0; nj < 4; ++nj) {
                #pragma unroll
                for (int hf = 0; hf < 2; ++hf) {
                    int icl = wn * 32 + nj * 8 + hf * 4 + q;
                    float* cc = c[mi][nj * 2 + hf];
                    {
                        int r = wm * 32 + mi * 16 + r0;
                        float g = cc[0], u = cc[1];
                        hst[r * 72 + icl] = __float2half_rn(g / (1.f + __expf(-g)) * u * 0.03125f);
                    }
                    {
                        int r = wm * 32 + mi * 16 + r0 + 8;
                        float g = cc[2], u = cc[3];
                        hst[r * 72 + icl] = __float2half_rn(g / (1.f + __expf(-g)) * u * 0.03125f);
                    }
                }
            }
        }
        __syncthreads();
        #pragma unroll
        for (int it = 0; it < 4; ++it) {
            int j = tid + it * 256;
            int r = j >> 3, part = j & 7;
            if (r < rows) {
                const char* src = (const char*)hst + r * 144 + part * 16;
                uint4 v = *(const uint4*)src;
                *(uint4*)(&g_h[s_pair[r]][i0 + part * 8]) = v;
            }
        }
    }
}

// =========================================================================
// down: M=128 pairs, N=128 h-outputs, K chunks of 64 over NI=1408
// output: atomicAdd into out (exactly 2 contributions per element -> deterministic)
// =========================================================================
__global__ void __launch_bounds__(256, 2) k_down(
    const float* __restrict__ ds_,
    const float* __restrict__ topk_w,
    float*       __restrict__ out)
{
    int e = blockIdx.y / MB, mb = blockIdx.y % MB;
    int start = g_off[e], end = g_off[e + 1];
    int m0 = start + mb * BM;
    if (m0 >= end) return;
    int rows = min(BM, end - m0);
    int h0 = blockIdx.x * 128;

    extern __shared__ __align__(16) char smem[];
    uint32_t sb = smem_u32(smem);
    float* rtab = (float*)(smem + 65536);
    int* s_pair = (int*)(smem + 65536 + 5632);

    int tid = threadIdx.x, warp = tid >> 5, lane = tid & 31;
    if (tid < BM)
        s_pair[tid] = g_pairs[m0 + (tid < rows ? tid : 0)];
    for (int t = tid; t < 11 * 128; t += 256) {
        int g = t >> 7, n = t & 127;
        const float* arr = ds_ + (size_t)e * 11 * NH + h0 + n;
        float sg = arr[(size_t)g * NH];
        rtab[t] = (g < 10) ? sg / arr[(size_t)(g + 1) * NH] : sg * (16384.f * 32.f);
    }
    __syncthreads();

    int ar = tid >> 1, ac = (tid & 1) * 4;
    const __half* asrc = &g_h[s_pair[ar]][0];
    int wn_row = tid >> 1, wwb = (tid & 1) * 4;
    const __half* bsrc = &g_wd[e][h0 + wn_row][0];
    unsigned a_perm = ar & 7, b_perm = wn_row & 7;
    uint32_t a_st[2], b_st[2];
    a_st[0] = sb + A_BUF(0) + ar * 128;     a_st[1] = a_st[0] + 16384;
    b_st[0] = sb + B_BUF(0) + wn_row * 128; b_st[1] = b_st[0] + 16384;

    int wm = warp & 3, wn = warp >> 2;
    int q = lane & 3;
    uint32_t colk[4];
    #pragma unroll
    for (int kk = 0; kk < 4; ++kk)
        colk[kk] = (((kk * 2 + (lane >> 4)) ^ (lane & 7)) << 4);
    uint32_t a_base[2], b_base[2];
    a_base[0] = sb + A_BUF(0) + (wm * 32 + (lane & 15)) * 128;
    a_base[1] = a_base[0] + 16384;
    b_base[0] = sb + B_BUF(0) + (wn * 64 + (lane & 15)) * 128;
    b_base[1] = b_base[0] + 16384;
    int rt_half = wn * 32 + q;

    float c[2][8][4];
    #pragma unroll
    for (int a = 0; a < 2; a++)
        #pragma unroll
        for (int b = 0; b < 8; b++)
            #pragma unroll
            for (int z = 0; z < 4; z++) c[a][b][z] = 0.f;

    const int S = NI / 64;   // 22

    {
        #pragma unroll
        for (int j = 0; j < 4; ++j)
            cp_async16(a_st[0] + (((ac + j) ^ a_perm) << 4), asrc + (ac + j) * 8);
        #pragma unroll
        for (int j = 0; j < 4; ++j)
            cp_async16(b_st[0] + (((wwb + j) ^ b_perm) << 4), bsrc + (wwb + j) * 8);
        CP_COMMIT;
        CP_WAIT0;
    }
    __syncthreads();

    #pragma unroll 2
    for (int s = 0; s < S; ++s) {
        if (s + 1 < S) {
            int nb = (s + 1) & 1;
            #pragma unroll
            for (int j = 0; j < 4; ++j)
                cp_async16(a_st[nb] + (((ac + j) ^ a_perm) << 4),
                           asrc + (s + 1) * 64 + (ac + j) * 8);
            #pragma unroll
            for (int j = 0; j < 4; ++j)
                cp_async16(b_st[nb] + (((wwb + j) ^ b_perm) << 4),
                           bsrc + (s + 1) * 64 + (wwb + j) * 8);
            CP_COMMIT;
        }
        {
            uint32_t ab = a_base[s & 1];
            uint32_t bb = b_base[s & 1];
            #pragma unroll
            for (int kk = 0; kk < 4; ++kk) {
                unsigned a0[4], a1[4];
                ldsm4(a0, ab + colk[kk]);
                ldsm4(a1, ab + 2048 + colk[kk]);
                #pragma unroll
                for (int nj = 0; nj < 4; ++nj) {
                    unsigned bf[4];
                    ldsm4(bf, bb + nj * 2048 + colk[kk]);
                    unsigned b0[2] = {bf[0], bf[2]}, b1[2] = {bf[1], bf[3]};
                    mma16816(c[0][nj * 2 + 0], a0, b0);
                    mma16816(c[0][nj * 2 + 1], a0, b1);
                    mma16816(c[1][nj * 2 + 0], a1, b0);
                    mma16816(c[1][nj * 2 + 1], a1, b1);
                }
            }
        }
        if (s & 1) {
            const float2* rt = (const float2*)(rtab + (s >> 1) * 128);
            #pragma unroll
            for (int nj = 0; nj < 4; ++nj)
                #pragma unroll
                for (int hf = 0; hf < 2; ++hf) {
                    float2 r2 = rt[rt_half + nj * 8 + hf * 4];
                    float* c0 = c[0][nj * 2 + hf];
                    float* c1 = c[1][nj * 2 + hf];
                    c0[0] *= r2.x; c0[1] *= r2.y; c0[2] *= r2.x; c0[3] *= r2.y;
                    c1[0] *= r2.x; c1[1] *= r2.y; c1[2] *= r2.x; c1[3] *= r2.y;
                }
        }
        if (s + 1 < S) { CP_WAIT0; }
        __syncthreads();
    }

    // epilogue: atomicAdd weighted outputs directly into out[token][h]
    int r0 = lane >> 2;
    #pragma unroll
    for (int mi = 0; mi < 2; ++mi) {
        int ra  = wm * 32 + mi * 16 + r0;
        int rbr = ra + 8;
        #pragma unroll
        for (int nj = 0; nj < 4; ++nj) {
            #pragma unroll
            for (int hf = 0; hf < 2; ++hf) {
                int col = h0 + wn * 64 + nj * 16 + hf * 8 + 2 * q;
                float* cc = c[mi][nj * 2 + hf];
                if (ra < rows) {
                    int pr = s_pair[ra];
                    float w = topk_w[pr];
                    float* dst = out + (size_t)(pr >> 1) * NH + col;
                    atomicAdd(dst,     cc[0] * w);
                    atomicAdd(dst + 1, cc[1] * w);
                }
                if (rbr < rows) {
                    int pr = s_pair[rbr];
                    float w = topk_w[pr];
                    float* dst = out + (size_t)(pr >> 1) * NH + col;
                    atomicAdd(dst,     cc[2] * w);
                    atomicAdd(dst + 1, cc[3] * w);
                }
            }
        }
    }
}

extern "C" void kernel_launch(void* const* d_in, const int* in_sizes, int n_in,
                              void* d_out, int out_size) {
    const float*    x           = (const float*)d_in[0];
    const unsigned* gate_packed = (const unsigned*)d_in[1];
    const float*    gate_scales = (const float*)d_in[2];
    const unsigned* up_packed   = (const unsigned*)d_in[3];
    const float*    up_scales   = (const float*)d_in[4];
    const unsigned* down_packed = (const unsigned*)d_in[5];
    const float*    down_scales = (const float*)d_in[6];
    const int*      topk_idx    = (const int*)d_in[7];
    const float*    topk_w      = (const float*)d_in[8];
    float*          out         = (float*)d_out;

    cudaFuncSetAttribute(k_gateup, cudaFuncAttributeMaxDynamicSharedMemorySize, GU_SMEM);
    cudaFuncSetAttribute(k_down,   cudaFuncAttributeMaxDynamicSharedMemorySize, DN_SMEM);

    cudaMemsetAsync(out, 0, (size_t)out_size * sizeof(float));
    k_front<<<NB_PREP + NB_GU + NB_DN + 1, 256>>>(x, gate_packed, up_packed,
                                                  down_packed, topk_idx);

    dim3 g1(NI / 64, NE * MB);
    k_gateup<<<g1, 256, GU_SMEM>>>(gate_scales, up_scales);

    dim3 g2(NH / 128, NE * MB);
    k_down<<<g2, 256, DN_SMEM>>>(down_scales, topk_w, out);
}

// round 17
// speedup vs baseline: 1.1403x; 1.1403x over previous
#include <cuda_runtime.h>
#include <cuda_fp16.h>
#include <cstdint>

// Problem constants
#define NE 8
#define NH 2048
#define NI 1408
#define NT 2048
#define NK 2
#define NG 128
#define NPAIR (NT * NK)   // 4096
#define BM 128
#define MB (NPAIR / BM)   // 32

// ---------------- scratch ----------------
__device__ int    g_off[NE + 1];
__device__ int    g_pairs[NPAIR];
__device__ __half g_xh[NT][NH];     // x in fp16
__device__ __half g_h[NPAIR][NI];   // silu(g)*u / 32

// ---------------- helpers ----------------
__device__ __forceinline__ uint32_t smem_u32(const void* p) {
    uint32_t a;
    asm("{ .reg .u64 t; cvta.to.shared.u64 t, %1; cvt.u32.u64 %0, t; }" : "=r"(a) : "l"(p));
    return a;
}
__device__ __forceinline__ void ldsm4(unsigned* r, uint32_t addr) {
    asm volatile("ldmatrix.sync.aligned.m8n8.x4.shared.b16 {%0,%1,%2,%3},[%4];"
                 : "=r"(r[0]), "=r"(r[1]), "=r"(r[2]), "=r"(r[3]) : "r"(addr));
}
__device__ __forceinline__ void mma16816(float* c, const unsigned* a, const unsigned* b) {
    asm volatile(
        "mma.sync.aligned.m16n8k16.row.col.f32.f16.f16.f32 "
        "{%0,%1,%2,%3},{%4,%5,%6,%7},{%8,%9},{%0,%1,%2,%3};"
        : "+f"(c[0]), "+f"(c[1]), "+f"(c[2]), "+f"(c[3])
        : "r"(a[0]), "r"(a[1]), "r"(a[2]), "r"(a[3]), "r"(b[0]), "r"(b[1]));
}
__device__ __forceinline__ void cp_async16(uint32_t dst, const void* src) {
    asm volatile("cp.async.cg.shared.global [%0], [%1], 16;" :: "r"(dst), "l"(src));
}
#define CP_COMMIT asm volatile("cp.async.commit_group;" ::: "memory")
#define CP_WAIT0  asm volatile("cp.async.wait_group 0;" ::: "memory")

// 8 e2m1 nibbles -> 8 fp16 encoding value * 2^-14 (exact, incl. subnormals).
__device__ __forceinline__ unsigned dec_pair(unsigned u) {
    return ((u << 9) & 0x0E000E00u) | ((u << 12) & 0x80008000u);
}
__device__ __forceinline__ uint4 dec_word_raw(unsigned p) {
    unsigned e = p & 0x0F0F0F0Fu;
    unsigned o = (p >> 4) & 0x0F0F0F0Fu;
    uint4 r;
    r.x = dec_pair(__byte_perm(e, o, 0x0400));
    r.y = dec_pair(__byte_perm(e, o, 0x0501));
    r.z = dec_pair(__byte_perm(e, o, 0x0602));
    r.w = dec_pair(__byte_perm(e, o, 0x0703));
    return r;
}
__device__ __forceinline__ uint4 f8_to_h8(float4 v0, float4 v1) {
    __half2 a = __floats2half2_rn(v0.x, v0.y);
    __half2 b = __floats2half2_rn(v0.z, v0.w);
    __half2 c = __floats2half2_rn(v1.x, v1.y);
    __half2 d = __floats2half2_rn(v1.z, v1.w);
    return make_uint4(*(unsigned*)&a, *(unsigned*)&b, *(unsigned*)&c, *(unsigned*)&d);
}

// ---------------- fused prep (x->fp16, MLP=4) + routing ----------------
#define NB_PREP (NT * NH / 16 / 256)   // 1024

__global__ void k_prep_route(const float* __restrict__ x,
                             const int* __restrict__ topk_idx) {
    if (blockIdx.x < NB_PREP) {
        int idx = blockIdx.x * 256 + threadIdx.x;     // over NT*NH/16
        const float4* p = reinterpret_cast<const float4*>(x) + (size_t)idx * 4;
        float4 v0 = p[0], v1 = p[1], v2 = p[2], v3 = p[3];
        uint4* dst = reinterpret_cast<uint4*>(&g_xh[0][0] + (size_t)idx * 16);
        dst[0] = f8_to_h8(v0, v1);
        dst[1] = f8_to_h8(v2, v3);
        return;
    }
    __shared__ int s_cnt[NE];
    __shared__ int s_off[NE + 1];
    int tid = threadIdx.x;
    if (tid < NE) s_cnt[tid] = 0;
    __syncthreads();
    for (int p = tid; p < NPAIR; p += 256)
        atomicAdd(&s_cnt[topk_idx[p]], 1);
    __syncthreads();
    if (tid == 0) {
        int acc = 0;
        for (int e = 0; e < NE; e++) { s_off[e] = acc; acc += s_cnt[e]; s_cnt[e] = 0; }
        s_off[NE] = acc;
        for (int e = 0; e <= NE; e++) g_off[e] = s_off[e];
    }
    __syncthreads();
    for (int p = tid; p < NPAIR; p += 256) {
        int e = topk_idx[p];
        int pos = s_off[e] + atomicAdd(&s_cnt[e], 1);
        g_pairs[pos] = p;
    }
}

// =========================================================================
// smem: A 2x16KB @0/16384 ; B 2x16KB @32768/49152 ; rtab @65536 ; tables
// =========================================================================
#define A_BUF(i) ((i) * 16384)
#define B_BUF(i) (32768 + (i) * 16384)
#define GU_SMEM (65536 + 8192 + 1024)
#define DN_SMEM (65536 + 5632 + 512)

__global__ void __launch_bounds__(256, 2) k_gateup(
    const unsigned* __restrict__ gp_,
    const float*    __restrict__ gs_,
    const unsigned* __restrict__ up_,
    const float*    __restrict__ us_)
{
    int e = blockIdx.y / MB, mb = blockIdx.y % MB;
    int start = g_off[e], end = g_off[e + 1];
    int m0 = start + mb * BM;
    if (m0 >= end) return;
    int rows = min(BM, end - m0);
    int i0 = blockIdx.x * 64;

    extern __shared__ __align__(16) char smem[];
    uint32_t sb = smem_u32(smem);
    float* rtab = (float*)(smem + 65536);
    int* s_pair = (int*)(smem + 65536 + 8192);
    int* s_tok  = (int*)(smem + 65536 + 8192 + 512);

    int tid = threadIdx.x, warp = tid >> 5, lane = tid & 31;
    if (tid < BM) {
        int pr = g_pairs[m0 + (tid < rows ? tid : 0)];
        s_pair[tid] = pr;
        s_tok[tid]  = pr / NK;
    }
    for (int t = tid; t < 16 * 128; t += 256) {
        int g = t >> 7, n = t & 127;
        const float* arr = ((n & 1) ? us_ : gs_) + (size_t)e * 16 * NI + (i0 + (n >> 1));
        float sg = arr[(size_t)g * NI];
        rtab[t] = (g < 15) ? sg / arr[(size_t)(g + 1) * NI] : sg * 16384.f;
    }
    __syncthreads();

    const unsigned* gp = gp_ + (size_t)e * NI * (NH / 8);
    const unsigned* up = up_ + (size_t)e * NI * (NH / 8);

    // staging roles
    int ar = tid >> 1, ac = (tid & 1) * 4;
    const __half* asrc = &g_xh[s_tok[ar]][0];
    int wn_row = tid >> 1, wwb = (tid & 1) * 4;
    int ig = i0 + (wn_row >> 1);
    const unsigned* wsrc = ((wn_row & 1) ? up : gp) + (size_t)ig * (NH / 8);
    unsigned a_perm = ar & 7, b_perm = wn_row & 7;
    uint32_t a_st[2], b_st[2];
    a_st[0] = sb + A_BUF(0) + ar * 128;   a_st[1] = a_st[0] + 16384;
    b_st[0] = sb + B_BUF(0) + wn_row * 128; b_st[1] = b_st[0] + 16384;

    // mma roles: 4 m-warps x 2 n-warps
    int wm = warp & 3, wn = warp >> 2;
    int q = lane & 3;
    uint32_t colk[4];
    #pragma unroll
    for (int kk = 0; kk < 4; ++kk)
        colk[kk] = (((kk * 2 + (lane >> 4)) ^ (lane & 7)) << 4);
    uint32_t a_base[2], b_base[2];
    a_base[0] = sb + A_BUF(0) + (wm * 32 + (lane & 15)) * 128;
    a_base[1] = a_base[0] + 16384;
    b_base[0] = sb + B_BUF(0) + (wn * 64 + (lane & 15)) * 128;
    b_base[1] = b_base[0] + 16384;
    int rt_half = wn * 32 + q;

    float c[2][8][4];
    #pragma unroll
    for (int a = 0; a < 2; a++)
        #pragma unroll
        for (int b = 0; b < 8; b++)
            #pragma unroll
            for (int z = 0; z < 4; z++) c[a][b][z] = 0.f;

    const int S = NH / 64;   // 32
    uint4 wv_cur, wv_nxt;

    // ---- prologue: A0 in flight; B0 decoded; w[1] in regs
    {
        #pragma unroll
        for (int j = 0; j < 4; ++j)
            cp_async16(a_st[0] + (((ac + j) ^ a_perm) << 4), asrc + (ac + j) * 8);
        CP_COMMIT;
        uint4 w0 = *(const uint4*)(wsrc + wwb);
        unsigned wds[4] = {w0.x, w0.y, w0.z, w0.w};
        #pragma unroll
        for (int j = 0; j < 4; ++j)
            *(uint4*)(smem + B_BUF(0) + wn_row * 128 + (((wwb + j) ^ b_perm) << 4)) = dec_word_raw(wds[j]);
        wv_cur = *(const uint4*)(wsrc + 8 + wwb);
        CP_WAIT0;
    }
    __syncthreads();

    #pragma unroll 2
    for (int s = 0; s < S; ++s) {
        if (s + 1 < S) {
            #pragma unroll
            for (int j = 0; j < 4; ++j)
                cp_async16(a_st[(s + 1) & 1] + (((ac + j) ^ a_perm) << 4),
                           asrc + (s + 1) * 64 + (ac + j) * 8);
            CP_COMMIT;
            unsigned wds[4] = {wv_cur.x, wv_cur.y, wv_cur.z, wv_cur.w};
            #pragma unroll
            for (int j = 0; j < 4; ++j)
                *(uint4*)((char*)smem + (b_st[(s + 1) & 1] - sb) + (((wwb + j) ^ b_perm) << 4)) = dec_word_raw(wds[j]);
        }
        if (s + 2 < S)
            wv_nxt = *(const uint4*)(wsrc + (s + 2) * 8 + wwb);
        // MMA on A[s&1], B[s&1]
        {
            uint32_t ab = a_base[s & 1];
            uint32_t bb = b_base[s & 1];
            #pragma unroll
            for (int kk = 0; kk < 4; ++kk) {
                unsigned a0[4], a1[4];
                ldsm4(a0, ab + colk[kk]);
                ldsm4(a1, ab + 2048 + colk[kk]);
                #pragma unroll
                for (int nj = 0; nj < 4; ++nj) {
                    unsigned bf[4];
                    ldsm4(bf, bb + nj * 2048 + colk[kk]);
                    unsigned b0[2] = {bf[0], bf[2]}, b1[2] = {bf[1], bf[3]};
                    mma16816(c[0][nj * 2 + 0], a0, b0);
                    mma16816(c[0][nj * 2 + 1], a0, b1);
                    mma16816(c[1][nj * 2 + 0], a1, b0);
                    mma16816(c[1][nj * 2 + 1], a1, b1);
                }
            }
        }
        if (s & 1) {
            const float2* rt = (const float2*)(rtab + (s >> 1) * 128);
            #pragma unroll
            for (int nj = 0; nj < 4; ++nj)
                #pragma unroll
                for (int hf = 0; hf < 2; ++hf) {
                    float2 r2 = rt[rt_half + nj * 8 + hf * 4];
                    float* c0 = c[0][nj * 2 + hf];
                    float* c1 = c[1][nj * 2 + hf];
                    c0[0] *= r2.x; c0[1] *= r2.y; c0[2] *= r2.x; c0[3] *= r2.y;
                    c1[0] *= r2.x; c1[1] *= r2.y; c1[2] *= r2.x; c1[3] *= r2.y;
                }
        }
        wv_cur = wv_nxt;
        if (s + 1 < S) { CP_WAIT0; }
        __syncthreads();
    }

    // ---- epilogue: silu(g)*u -> smem (row stride 72 halves = 144B, 16B aligned),
    //      then coalesced 16B writes to g_h
    {
        __half* hst = (__half*)smem;   // 128 rows x 64 cols, row stride 72 halves
        int r0 = lane >> 2;
        #pragma unroll
        for (int mi = 0; mi < 2; ++mi) {
            #pragma unroll
            for (int nj = 0; nj < 4; ++nj) {
                #pragma unroll
                for (int hf = 0; hf < 2; ++hf) {
                    int icl = wn * 32 + nj * 8 + hf * 4 + q;
                    float* cc = c[mi][nj * 2 + hf];
                    {
                        int r = wm * 32 + mi * 16 + r0;
                        float g = cc[0], u = cc[1];
                        hst[r * 72 + icl] = __float2half_rn(g / (1.f + __expf(-g)) * u * 0.03125f);
                    }
                    {
                        int r = wm * 32 + mi * 16 + r0 + 8;
                        float g = cc[2], u = cc[3];
                        hst[r * 72 + icl] = __float2half_rn(g / (1.f + __expf(-g)) * u * 0.03125f);
                    }
                }
            }
        }
        __syncthreads();
        // coalesced copy: 128 rows x 8 uint4 (16B) each
        #pragma unroll
        for (int it = 0; it < 4; ++it) {
            int j = tid + it * 256;            // 0..1023
            int r = j >> 3, part = j & 7;
            if (r < rows) {
                const char* src = (const char*)hst + r * 144 + part * 16;
                uint4 v = *(const uint4*)src;
                *(uint4*)(&g_h[s_pair[r]][i0 + part * 8]) = v;
            }
        }
    }
}

// =========================================================================
// down: M=128 pairs, N=128 h-outputs, K chunks of 64 over NI=1408
// output: atomicAdd into out (exactly 2 contributions per element -> deterministic)
// =========================================================================
__global__ void __launch_bounds__(256, 2) k_down(
    const unsigned* __restrict__ dp_,
    const float*    __restrict__ ds_,
    const float*    __restrict__ topk_w,
    float*          __restrict__ out)
{
    int e = blockIdx.y / MB, mb = blockIdx.y % MB;
    int start = g_off[e], end = g_off[e + 1];
    int m0 = start + mb * BM;
    if (m0 >= end) return;
    int rows = min(BM, end - m0);
    int h0 = blockIdx.x * 128;

    extern __shared__ __align__(16) char smem[];
    uint32_t sb = smem_u32(smem);
    float* rtab = (float*)(smem + 65536);
    int* s_pair = (int*)(smem + 65536 + 5632);

    int tid = threadIdx.x, warp = tid >> 5, lane = tid & 31;
    if (tid < BM)
        s_pair[tid] = g_pairs[m0 + (tid < rows ? tid : 0)];
    for (int t = tid; t < 11 * 128; t += 256) {
        int g = t >> 7, n = t & 127;
        const float* arr = ds_ + (size_t)e * 11 * NH + h0 + n;
        float sg = arr[(size_t)g * NH];
        rtab[t] = (g < 10) ? sg / arr[(size_t)(g + 1) * NH] : sg * (16384.f * 32.f);
    }
    __syncthreads();

    const unsigned* dp = dp_ + (size_t)e * NH * (NI / 8);

    int ar = tid >> 1, ac = (tid & 1) * 4;
    const __half* asrc = &g_h[s_pair[ar]][0];
    int wn_row = tid >> 1, wwb = (tid & 1) * 4;
    const unsigned* wsrc = dp + (size_t)(h0 + wn_row) * (NI / 8);
    unsigned a_perm = ar & 7, b_perm = wn_row & 7;
    uint32_t a_st[2], b_st[2];
    a_st[0] = sb + A_BUF(0) + ar * 128;   a_st[1] = a_st[0] + 16384;
    b_st[0] = sb + B_BUF(0) + wn_row * 128; b_st[1] = b_st[0] + 16384;

    int wm = warp & 3, wn = warp >> 2;
    int q = lane & 3;
    uint32_t colk[4];
    #pragma unroll
    for (int kk = 0; kk < 4; ++kk)
        colk[kk] = (((kk * 2 + (lane >> 4)) ^ (lane & 7)) << 4);
    uint32_t a_base[2], b_base[2];
    a_base[0] = sb + A_BUF(0) + (wm * 32 + (lane & 15)) * 128;
    a_base[1] = a_base[0] + 16384;
    b_base[0] = sb + B_BUF(0) + (wn * 64 + (lane & 15)) * 128;
    b_base[1] = b_base[0] + 16384;
    int rt_half = wn * 32 + q;

    float c[2][8][4];
    #pragma unroll
    for (int a = 0; a < 2; a++)
        #pragma unroll
        for (int b = 0; b < 8; b++)
            #pragma unroll
            for (int z = 0; z < 4; z++) c[a][b][z] = 0.f;

    const int S = NI / 64;   // 22
    uint4 wv_cur, wv_nxt;

    {
        #pragma unroll
        for (int j = 0; j < 4; ++j)
            cp_async16(a_st[0] + (((ac + j) ^ a_perm) << 4), asrc + (ac + j) * 8);
        CP_COMMIT;
        uint4 w0 = *(const uint4*)(wsrc + wwb);
        unsigned wds[4] = {w0.x, w0.y, w0.z, w0.w};
        #pragma unroll
        for (int j = 0; j < 4; ++j)
            *(uint4*)(smem + B_BUF(0) + wn_row * 128 + (((wwb + j) ^ b_perm) << 4)) = dec_word_raw(wds[j]);
        wv_cur = *(const uint4*)(wsrc + 8 + wwb);
        CP_WAIT0;
    }
    __syncthreads();

    #pragma unroll 2
    for (int s = 0; s < S; ++s) {
        if (s + 1 < S) {
            #pragma unroll
            for (int j = 0; j < 4; ++j)
                cp_async16(a_st[(s + 1) & 1] + (((ac + j) ^ a_perm) << 4),
                           asrc + (s + 1) * 64 + (ac + j) * 8);
            CP_COMMIT;
            unsigned wds[4] = {wv_cur.x, wv_cur.y, wv_cur.z, wv_cur.w};
            #pragma unroll
            for (int j = 0; j < 4; ++j)
                *(uint4*)((char*)smem + (b_st[(s + 1) & 1] - sb) + (((wwb + j) ^ b_perm) << 4)) = dec_word_raw(wds[j]);
        }
        if (s + 2 < S)
            wv_nxt = *(const uint4*)(wsrc + (s + 2) * 8 + wwb);
        {
            uint32_t ab = a_base[s & 1];
            uint32_t bb = b_base[s & 1];
            #pragma unroll
            for (int kk = 0; kk < 4; ++kk) {
                unsigned a0[4], a1[4];
                ldsm4(a0, ab + colk[kk]);
                ldsm4(a1, ab + 2048 + colk[kk]);
                #pragma unroll
                for (int nj = 0; nj < 4; ++nj) {
                    unsigned bf[4];
                    ldsm4(bf, bb + nj * 2048 + colk[kk]);
                    unsigned b0[2] = {bf[0], bf[2]}, b1[2] = {bf[1], bf[3]};
                    mma16816(c[0][nj * 2 + 0], a0, b0);
                    mma16816(c[0][nj * 2 + 1], a0, b1);
                    mma16816(c[1][nj * 2 + 0], a1, b0);
                    mma16816(c[1][nj * 2 + 1], a1, b1);
                }
            }
        }
        if (s & 1) {
            const float2* rt = (const float2*)(rtab + (s >> 1) * 128);
            #pragma unroll
            for (int nj = 0; nj < 4; ++nj)
                #pragma unroll
                for (int hf = 0; hf < 2; ++hf) {
                    float2 r2 = rt[rt_half + nj * 8 + hf * 4];
                    float* c0 = c[0][nj * 2 + hf];
                    float* c1 = c[1][nj * 2 + hf];
                    c0[0] *= r2.x; c0[1] *= r2.y; c0[2] *= r2.x; c0[3] *= r2.y;
                    c1[0] *= r2.x; c1[1] *= r2.y; c1[2] *= r2.x; c1[3] *= r2.y;
                }
        }
        wv_cur = wv_nxt;
        if (s + 1 < S) { CP_WAIT0; }
        __syncthreads();
    }

    // epilogue: atomicAdd weighted outputs directly into out[token][h]
    int r0 = lane >> 2;
    #pragma unroll
    for (int mi = 0; mi < 2; ++mi) {
        int ra  = wm * 32 + mi * 16 + r0;
        int rbr = ra + 8;
        #pragma unroll
        for (int nj = 0; nj < 4; ++nj) {
            #pragma unroll
            for (int hf = 0; hf < 2; ++hf) {
                int col = h0 + wn * 64 + nj * 16 + hf * 8 + 2 * q;
                float* cc = c[mi][nj * 2 + hf];
                if (ra < rows) {
                    int pr = s_pair[ra];
                    float w = topk_w[pr];
                    float* dst = out + (size_t)(pr >> 1) * NH + col;
                    atomicAdd(dst,     cc[0] * w);
                    atomicAdd(dst + 1, cc[1] * w);
                }
                if (rbr < rows) {
                    int pr = s_pair[rbr];
                    float w = topk_w[pr];
                    float* dst = out + (size_t)(pr >> 1) * NH + col;
                    atomicAdd(dst,     cc[2] * w);
                    atomicAdd(dst + 1, cc[3] * w);
                }
            }
        }
    }
}

extern "C" void kernel_launch(void* const* d_in, const int* in_sizes, int n_in,
                              void* d_out, int out_size) {
    const float*    x           = (const float*)d_in[0];
    const unsigned* gate_packed = (const unsigned*)d_in[1];
    const float*    gate_scales = (const float*)d_in[2];
    const unsigned* up_packed   = (const unsigned*)d_in[3];
    const float*    up_scales   = (const float*)d_in[4];
    const unsigned* down_packed = (const unsigned*)d_in[5];
    const float*    down_scales = (const float*)d_in[6];
    const int*      topk_idx    = (const int*)d_in[7];
    const float*    topk_w      = (const float*)d_in[8];
    float*          out         = (float*)d_out;

    cudaFuncSetAttribute(k_gateup, cudaFuncAttributeMaxDynamicSharedMemorySize, GU_SMEM);
    cudaFuncSetAttribute(k_down,   cudaFuncAttributeMaxDynamicSharedMemorySize, DN_SMEM);

    cudaMemsetAsync(out, 0, (size_t)out_size * sizeof(float));
    k_prep_route<<<NB_PREP + 1, 256>>>(x, topk_idx);

    dim3 g1(NI / 64, NE * MB);
    k_gateup<<<g1, 256, GU_SMEM>>>(gate_packed, gate_scales, up_packed, up_scales);

    dim3 g2(NH / 128, NE * MB);
    k_down<<<g2, 256, DN_SMEM>>>(down_packed, down_scales, topk_w, out);
}